// round 9
// baseline (speedup 1.0000x reference)
#include <cuda_runtime.h>
#include <cuda_fp16.h>
#include <cstdint>
#include <math.h>

#define B_DIM 64
#define S_DIM 2048
#define D_DIM 512

#define BLK_S 128
#define NTHREADS 256
#define NMACRO 32            // 4 ei * 8 kt (k-tile = 64)
#define NSTAGE 3
#define STG_WORDS 8192       // A 4096 words (8192 fp16) + B 4096 words
#define CONST_OFF (NSTAGE * STG_WORDS)          // 24576
#define SMEM_WORDS (CONST_OFF + 1664)           // 104960 B -> 2 CTAs/SM

// scratch (no device mallocs; __device__ globals are the sanctioned path)
__device__ uint32_t g_w16[NMACRO * 4096];   // W fp16, fragment-ordered
__device__ float    g_qpb[B_DIM * D_DIM];   // q + Wq_b + Wr_b

// ---------------------------------------------------------------------------
// prep: [0,256): W -> fragment-ordered fp16 pairs.  [256,1280): q projection.
// ---------------------------------------------------------------------------
__global__ void prep_kernel(const float* __restrict__ Wr_w,
                            const float* __restrict__ query,
                            const float* __restrict__ Wq_w,
                            const float* __restrict__ Wq_b,
                            const float* __restrict__ Wr_b) {
    if (blockIdx.x < 256) {
        int o = blockIdx.x * 256 + threadIdx.x;
        #pragma unroll
        for (int it = 0; it < 2; it++, o += 65536) {
            const int g = o >> 12, rem = o & 4095;
            const int c = rem >> 2, w = rem & 3;
            const int lane = c & 31, t = c >> 5;
            const int j = t & 3, we = (t >> 2) & 1, ks = t >> 3;
            const int ei = g >> 3, kt = g & 7;
            const int tn = j * 2 + (w >> 1);
            const int e = ei * 128 + we * 64 + tn * 8 + (lane >> 2);
            const int k = kt * 64 + ks * 16 + 2 * (lane & 3) + (w & 1) * 8;
            __half2 h = __floats2half2_rn(Wr_w[e * D_DIM + k], Wr_w[e * D_DIM + k + 1]);
            g_w16[o] = *reinterpret_cast<uint32_t*>(&h);
        }
    } else {
        __shared__ float qs[D_DIM];
        const int id2 = blockIdx.x - 256;
        const int b = id2 & 63;
        const int eblk = id2 >> 6;
        const int tid = threadIdx.x, lane = tid & 31, w = tid >> 5;
        for (int i = tid; i < D_DIM; i += 256) qs[i] = query[(size_t)b * D_DIM + i];
        __syncthreads();
        const int e0 = eblk * 32 + w * 4;
        #pragma unroll
        for (int k = 0; k < 4; k++) {
            const int e = e0 + k;
            const float* wr = Wq_w + (size_t)e * D_DIM;
            float s = 0.f;
            #pragma unroll
            for (int d = lane; d < D_DIM; d += 32) s += qs[d] * wr[d];
            #pragma unroll
            for (int o = 16; o; o >>= 1) s += __shfl_xor_sync(0xffffffffu, s, o);
            if (lane == 0) g_qpb[b * D_DIM + e] = s + Wq_b[e] + Wr_b[e];
        }
    }
}

// ---------------------------------------------------------------------------
// helpers
// ---------------------------------------------------------------------------
__device__ __forceinline__ void cp16(void* dst, const void* src) {
    unsigned s = (unsigned)__cvta_generic_to_shared(dst);
    asm volatile("cp.async.cg.shared.global [%0], [%1], 16;"
                 :: "r"(s), "l"(src) : "memory");
}
__device__ __forceinline__ float tanha(float x) {
    float y;
    asm("tanh.approx.f32 %0, %1;" : "=f"(y) : "f"(x));
    return y;
}
__device__ __forceinline__ void ldm4(unsigned& r0, unsigned& r1, unsigned& r2,
                                     unsigned& r3, unsigned addr) {
    asm volatile("ldmatrix.sync.aligned.m8n8.x4.shared.b16 {%0,%1,%2,%3}, [%4];"
                 : "=r"(r0), "=r"(r1), "=r"(r2), "=r"(r3) : "r"(addr));
}
__device__ __forceinline__ uint4 pack8(const float4 v0, const float4 v1) {
    __half2 h0 = __floats2half2_rn(v0.x, v0.y);
    __half2 h1 = __floats2half2_rn(v0.z, v0.w);
    __half2 h2 = __floats2half2_rn(v1.x, v1.y);
    __half2 h3 = __floats2half2_rn(v1.z, v1.w);
    uint4 o;
    o.x = *reinterpret_cast<uint32_t*>(&h0);
    o.y = *reinterpret_cast<uint32_t*>(&h1);
    o.z = *reinterpret_cast<uint32_t*>(&h2);
    o.w = *reinterpret_cast<uint32_t*>(&h3);
    return o;
}

#define SM_BIAS(i) sm[CONST_OFF + (i)]
#define SM_QPB(i)  sm[CONST_OFF + 512 + (i)]
#define SM_V(i)    sm[CONST_OFF + 1024 + (i)]
#define SM_L(i)    sm[CONST_OFF + 1536 + (i)]

// ---------------------------------------------------------------------------
// main: fp16 m16n8k16 HMMA; A converted fp32->fp16 on the fly (LDG+cvt+STS,
// one macro ahead); B via cp.async; 3-stage ring, one barrier per macro.
// ---------------------------------------------------------------------------
__global__ void __launch_bounds__(NTHREADS, 2)
attn_main(const float* __restrict__ ref,
          const float* __restrict__ Wr_b,
          const float* __restrict__ value,
          float* __restrict__ out_r,
          float* __restrict__ out_logits)
{
    extern __shared__ float sm[];
    const int tid    = threadIdx.x;
    const int lane   = tid & 31;
    const int warp   = tid >> 5;
    const int warp_s = warp & 3;
    const int warp_e = warp >> 2;
    const int b  = blockIdx.y;
    const int s0 = blockIdx.x * BLK_S;

    const float* aG32 = ref + ((size_t)b * S_DIM + s0) * D_DIM;
    float* outr_b = out_r + (size_t)b * D_DIM * S_DIM;

    // per-thread A-chunk coordinates (4 chunks of 8 floats -> 16B fp16)
    // chunk ca = tid + i*256: row = ca>>3, gc = ca&7
    int arow[4], asw[4];
    #pragma unroll
    for (int i = 0; i < 4; i++) {
        const int ca = tid + i * 256;
        arow[i] = ca >> 3;
        asw[i]  = arow[i] * 8 + ((ca & 7) ^ (arow[i] & 7));  // uint4 index in A stage
    }

    // ---- prologue: B cp.async for stages 0,1 ; A convert-fill stages 0,1 ----
    #pragma unroll
    for (int gp = 0; gp < 2; gp++) {
        uint32_t* sb = reinterpret_cast<uint32_t*>(sm) + gp * STG_WORDS + 4096;
        const uint32_t* bsrc = g_w16 + (size_t)gp * 4096;
        #pragma unroll
        for (int i = 0; i < 4; i++)
            cp16(sb + (tid + i * 256) * 4, bsrc + (tid + i * 256) * 4);
        asm volatile("cp.async.commit_group;" ::: "memory");

        uint4* sa = reinterpret_cast<uint4*>(sm + gp * STG_WORDS);
        const float4* a4 = reinterpret_cast<const float4*>(aG32 + (gp & 7) * 64);
        #pragma unroll
        for (int i = 0; i < 4; i++) {
            const float4 v0 = a4[arow[i] * 128 + ((tid + i * 256) & 7) * 2];
            const float4 v1 = a4[arow[i] * 128 + ((tid + i * 256) & 7) * 2 + 1];
            sa[asw[i]] = pack8(v0, v1);
        }
    }

    // epilogue constants
    for (int i = tid; i < D_DIM; i += NTHREADS) {
        SM_BIAS(i) = Wr_b[i];
        SM_QPB(i)  = g_qpb[b * D_DIM + i];
        SM_V(i)    = value[i];
    }
    if (tid < BLK_S) SM_L(tid) = 0.0f;

    asm volatile("cp.async.wait_group 1;" ::: "memory");
    __syncthreads();

    // ldmatrix per-thread selectors (invariant)
    const int lrow  = (lane & 15);
    const int lgsel = (lane >> 4) & 1;

    float acc[2][8][4];
    #pragma unroll
    for (int tm = 0; tm < 2; tm++)
        #pragma unroll
        for (int tn = 0; tn < 8; tn++)
            #pragma unroll
            for (int i = 0; i < 4; i++) acc[tm][tn][i] = 0.f;

    unsigned af[2][2][4];
    uint4    bq[4];
    float4   rA[4];     // A staging regs (two half-waves of 2 chunks)

    #pragma unroll 1
    for (int g = 0; g < NMACRO; g++) {
        const int slot = g % NSTAGE;
        const int tg   = (g + 2) % NSTAGE;
        const bool pf  = (g + 2 < NMACRO);

        const unsigned saddr =
            (unsigned)__cvta_generic_to_shared(sm + slot * STG_WORDS);
        const uint32_t* sb =
            reinterpret_cast<const uint32_t*>(sm) + slot * STG_WORDS + 4096;
        uint4* ta = reinterpret_cast<uint4*>(sm + tg * STG_WORDS);
        const float4* a4n =
            reinterpret_cast<const float4*>(aG32 + ((g + 2) & 7) * 64);

        // B prefetch for stage g+2 + first half of A LDG
        if (pf) {
            uint32_t* tb = reinterpret_cast<uint32_t*>(sm) + tg * STG_WORDS + 4096;
            const uint32_t* bsrc = g_w16 + (size_t)(g + 2) * 4096;
            #pragma unroll
            for (int i = 0; i < 4; i++)
                cp16(tb + (tid + i * 256) * 4, bsrc + (tid + i * 256) * 4);
            #pragma unroll
            for (int i = 0; i < 2; i++) {
                rA[2 * i]     = a4n[arow[i] * 128 + ((tid + i * 256) & 7) * 2];
                rA[2 * i + 1] = a4n[arow[i] * 128 + ((tid + i * 256) & 7) * 2 + 1];
            }
        }
        asm volatile("cp.async.commit_group;" ::: "memory");

        // ldmatrix slice 0 into buffer 0
        #pragma unroll
        for (int tm = 0; tm < 2; tm++) {
            const int r = warp_s * 32 + tm * 16 + lrow;
            const unsigned a = saddr + ((r * 8 + (lgsel ^ (r & 7))) << 4);
            ldm4(af[0][tm][0], af[0][tm][1], af[0][tm][2], af[0][tm][3], a);
        }

        #pragma unroll
        for (int ks = 0; ks < 4; ks++) {
            const int pb = ks & 1;
            const uint32_t* sbk = sb + ks * 1024 + warp_e * 512 + lane * 4;
            #pragma unroll
            for (int j = 0; j < 4; j++)
                bq[j] = *reinterpret_cast<const uint4*>(sbk + j * 128);
            if (ks < 3) {
                const int nb = pb ^ 1;
                const int gc = (ks + 1) * 2 + lgsel;
                #pragma unroll
                for (int tm = 0; tm < 2; tm++) {
                    const int r = warp_s * 32 + tm * 16 + lrow;
                    const unsigned a = saddr + ((r * 8 + (gc ^ (r & 7))) << 4);
                    ldm4(af[nb][tm][0], af[nb][tm][1], af[nb][tm][2], af[nb][tm][3], a);
                }
            }
            #pragma unroll
            for (int tm = 0; tm < 2; tm++)
                #pragma unroll
                for (int tn = 0; tn < 8; tn++) {
                    const unsigned b0 = (tn & 1) ? bq[tn >> 1].z : bq[tn >> 1].x;
                    const unsigned b1 = (tn & 1) ? bq[tn >> 1].w : bq[tn >> 1].y;
                    asm volatile(
                        "mma.sync.aligned.m16n8k16.row.col.f32.f16.f16.f32 "
                        "{%0,%1,%2,%3}, {%4,%5,%6,%7}, {%8,%9}, {%0,%1,%2,%3};"
                        : "+f"(acc[tm][tn][0]), "+f"(acc[tm][tn][1]),
                          "+f"(acc[tm][tn][2]), "+f"(acc[tm][tn][3])
                        : "r"(af[pb][tm][0]), "r"(af[pb][tm][1]),
                          "r"(af[pb][tm][2]), "r"(af[pb][tm][3]),
                          "r"(b0), "r"(b1));
                }

            // interleave A convert/store with MMA slices
            if (pf && ks == 1) {
                #pragma unroll
                for (int i = 0; i < 2; i++)
                    ta[asw[i]] = pack8(rA[2 * i], rA[2 * i + 1]);
                #pragma unroll
                for (int i = 2; i < 4; i++) {
                    rA[2 * (i - 2)]     = a4n[arow[i] * 128 + ((tid + i * 256) & 7) * 2];
                    rA[2 * (i - 2) + 1] = a4n[arow[i] * 128 + ((tid + i * 256) & 7) * 2 + 1];
                }
            }
            if (pf && ks == 3) {
                #pragma unroll
                for (int i = 2; i < 4; i++)
                    ta[asw[i]] = pack8(rA[2 * (i - 2)], rA[2 * (i - 2) + 1]);
            }
        }

        // -------- epilogue at each ei boundary --------
        if ((g & 7) == 7) {
            const int ei = g >> 3;
            float lp[2][2] = {{0.f, 0.f}, {0.f, 0.f}};
            const int sg0 = s0 + warp_s * 32 + (lane >> 2);
            #pragma unroll
            for (int tm = 0; tm < 2; tm++) {
                const int srow = sg0 + tm * 16;
                #pragma unroll
                for (int tn = 0; tn < 8; tn++) {
                    const int e = ei * 128 + warp_e * 64 + tn * 8 + 2 * (lane & 3);
                    const float b0 = SM_BIAS(e), b1 = SM_BIAS(e + 1);
                    const float a0 = acc[tm][tn][0], a1 = acc[tm][tn][1];
                    const float a2 = acc[tm][tn][2], a3 = acc[tm][tn][3];
                    outr_b[(size_t)e       * S_DIM + srow]     = a0 + b0;
                    outr_b[(size_t)(e + 1) * S_DIM + srow]     = a1 + b1;
                    outr_b[(size_t)e       * S_DIM + srow + 8] = a2 + b0;
                    outr_b[(size_t)(e + 1) * S_DIM + srow + 8] = a3 + b1;
                    const float q0 = SM_QPB(e), q1 = SM_QPB(e + 1);
                    const float v0 = SM_V(e), v1 = SM_V(e + 1);
                    lp[tm][0] += tanha(q0 + a0) * v0 + tanha(q1 + a1) * v1;
                    lp[tm][1] += tanha(q0 + a2) * v0 + tanha(q1 + a3) * v1;
                    acc[tm][tn][0] = 0.f; acc[tm][tn][1] = 0.f;
                    acc[tm][tn][2] = 0.f; acc[tm][tn][3] = 0.f;
                }
            }
            #pragma unroll
            for (int tm = 0; tm < 2; tm++)
                #pragma unroll
                for (int h = 0; h < 2; h++) {
                    float v = lp[tm][h];
                    v += __shfl_xor_sync(0xffffffffu, v, 1);
                    v += __shfl_xor_sync(0xffffffffu, v, 2);
                    if ((lane & 3) == 0)
                        atomicAdd(&SM_L(warp_s * 32 + tm * 16 + h * 8 + (lane >> 2)), v);
                }
        }

        // end-of-macro: publish stage g+1 (B arrival + A stores)
        asm volatile("cp.async.wait_group 1;" ::: "memory");
        __syncthreads();
    }

    if (tid < BLK_S)
        out_logits[(size_t)b * S_DIM + s0 + tid] = 10.0f * tanha(SM_L(tid));
}

// ---------------------------------------------------------------------------
// launch
// ---------------------------------------------------------------------------
extern "C" void kernel_launch(void* const* d_in, const int* in_sizes, int n_in,
                              void* d_out, int out_size) {
    const float* query = (const float*)d_in[0];
    const float* ref   = (const float*)d_in[1];
    const float* Wq_w  = (const float*)d_in[2];
    const float* Wq_b  = (const float*)d_in[3];
    const float* Wr_w  = (const float*)d_in[4];
    const float* Wr_b  = (const float*)d_in[5];
    const float* value = (const float*)d_in[6];
    (void)in_sizes; (void)n_in; (void)out_size;

    float* out        = (float*)d_out;
    float* out_r      = out;                                   // [B, D, S]
    float* out_logits = out + (size_t)B_DIM * D_DIM * S_DIM;   // [B, S]

    prep_kernel<<<1280, 256>>>(Wr_w, query, Wq_w, Wq_b, Wr_b);

    const size_t smem = SMEM_WORDS * sizeof(float);
    cudaFuncSetAttribute(attn_main, cudaFuncAttributeMaxDynamicSharedMemorySize,
                         (int)smem);
    dim3 grid(S_DIM / BLK_S, B_DIM);
    attn_main<<<grid, NTHREADS, smem>>>(ref, Wr_b, value, out_r, out_logits);
}

// round 10
// speedup vs baseline: 1.5697x; 1.5697x over previous
#include <cuda_runtime.h>
#include <cuda_fp16.h>
#include <cstdint>
#include <math.h>

#define B_DIM 64
#define S_DIM 2048
#define D_DIM 512

#define BLK_S 128
#define NTHREADS 256
#define NMACRO 32            // 4 ei * 8 kt (k-tile = 64)
#define NSTAGE 3
#define STG_WORDS 8192       // A 4096 words (8192 fp16) + B 4096 words
#define CONST_OFF (NSTAGE * STG_WORDS)          // 24576
#define SMEM_WORDS (CONST_OFF + 1664)           // 104960 B -> 2 CTAs/SM
#define NTILES 1024
#define DELTA 256            // producer lookahead (< 296 concurrent CTAs)

// scratch (no device mallocs; __device__ globals are the sanctioned path)
__device__ __half   g_ref16[(size_t)B_DIM * S_DIM * D_DIM];   // fp16 ref, tile-pipelined
__device__ uint32_t g_w16[NMACRO * 4096];                     // W fp16, fragment-ordered
__device__ float    g_qpb[B_DIM * D_DIM];                     // q + Wq_b + Wr_b
__device__ int      g_flags[NTILES];                          // tile-converted flags

// ---------------------------------------------------------------------------
// prep: [0,256): W -> fragment-ordered fp16 (+ zero flags in blocks 0-3)
//       [256,1280): q projection
// ---------------------------------------------------------------------------
__global__ void prep_kernel(const float* __restrict__ Wr_w,
                            const float* __restrict__ query,
                            const float* __restrict__ Wq_w,
                            const float* __restrict__ Wq_b,
                            const float* __restrict__ Wr_b) {
    if (blockIdx.x < 256) {
        if (blockIdx.x < 4) g_flags[blockIdx.x * 256 + threadIdx.x] = 0;
        int o = blockIdx.x * 256 + threadIdx.x;
        #pragma unroll
        for (int it = 0; it < 2; it++, o += 65536) {
            const int g = o >> 12, rem = o & 4095;
            const int c = rem >> 2, w = rem & 3;
            const int lane = c & 31, t = c >> 5;
            const int j = t & 3, we = (t >> 2) & 1, ks = t >> 3;
            const int ei = g >> 3, kt = g & 7;
            const int tn = j * 2 + (w >> 1);
            const int e = ei * 128 + we * 64 + tn * 8 + (lane >> 2);
            const int k = kt * 64 + ks * 16 + 2 * (lane & 3) + (w & 1) * 8;
            __half2 h = __floats2half2_rn(Wr_w[e * D_DIM + k], Wr_w[e * D_DIM + k + 1]);
            g_w16[o] = *reinterpret_cast<uint32_t*>(&h);
        }
    } else {
        __shared__ float qs[D_DIM];
        const int id2 = blockIdx.x - 256;
        const int b = id2 & 63;
        const int eblk = id2 >> 6;
        const int tid = threadIdx.x, lane = tid & 31, w = tid >> 5;
        for (int i = tid; i < D_DIM; i += 256) qs[i] = query[(size_t)b * D_DIM + i];
        __syncthreads();
        const int e0 = eblk * 32 + w * 4;
        #pragma unroll
        for (int k = 0; k < 4; k++) {
            const int e = e0 + k;
            const float* wr = Wq_w + (size_t)e * D_DIM;
            float s = 0.f;
            #pragma unroll
            for (int d = lane; d < D_DIM; d += 32) s += qs[d] * wr[d];
            #pragma unroll
            for (int o = 16; o; o >>= 1) s += __shfl_xor_sync(0xffffffffu, s, o);
            if (lane == 0) g_qpb[b * D_DIM + e] = s + Wq_b[e] + Wr_b[e];
        }
    }
}

// ---------------------------------------------------------------------------
// helpers
// ---------------------------------------------------------------------------
__device__ __forceinline__ void cp16(void* dst, const void* src) {
    unsigned s = (unsigned)__cvta_generic_to_shared(dst);
    asm volatile("cp.async.cg.shared.global [%0], [%1], 16;"
                 :: "r"(s), "l"(src) : "memory");
}
__device__ __forceinline__ float tanha(float x) {
    float y;
    asm("tanh.approx.f32 %0, %1;" : "=f"(y) : "f"(x));
    return y;
}
__device__ __forceinline__ void ldm4(unsigned& r0, unsigned& r1, unsigned& r2,
                                     unsigned& r3, unsigned addr) {
    asm volatile("ldmatrix.sync.aligned.m8n8.x4.shared.b16 {%0,%1,%2,%3}, [%4];"
                 : "=r"(r0), "=r"(r1), "=r"(r2), "=r"(r3) : "r"(addr));
}
__device__ __forceinline__ int ldacq(const int* p) {
    int v;
    asm volatile("ld.acquire.gpu.global.b32 %0, [%1];" : "=r"(v) : "l"(p) : "memory");
    return v;
}

// convert one 128x512 tile of ref (fp32) into g_ref16 (fp16)
__device__ __forceinline__ void convert_tile(const float* __restrict__ ref,
                                             int l, int tid) {
    const size_t base = (size_t)(l >> 4) * S_DIM * D_DIM
                      + (size_t)(l & 15) * BLK_S * D_DIM;
    const float4* src = reinterpret_cast<const float4*>(ref + base);
    uint2* dst = reinterpret_cast<uint2*>(g_ref16 + base);
    #pragma unroll 8
    for (int i = 0; i < 64; i++) {           // 64 * 256 = 16384 float4 = full tile
        const int idx = i * 256 + tid;
        const float4 v = src[idx];
        __half2 h0 = __floats2half2_rn(v.x, v.y);
        __half2 h1 = __floats2half2_rn(v.z, v.w);
        uint2 o;
        o.x = *reinterpret_cast<const uint32_t*>(&h0);
        o.y = *reinterpret_cast<const uint32_t*>(&h1);
        dst[idx] = o;
    }
}

#define SM_BIAS(i) sm[CONST_OFF + (i)]
#define SM_QPB(i)  sm[CONST_OFF + 512 + (i)]
#define SM_V(i)    sm[CONST_OFF + 1024 + (i)]
#define SM_L(i)    sm[CONST_OFF + 1536 + (i)]

// ---------------------------------------------------------------------------
// main: cross-wave pipelined conversion (producer = CTA lin converts lin+DELTA)
//       + R6 fp16 HMMA mainloop (3-stage cp.async ring, ldmatrix A)
// ---------------------------------------------------------------------------
__global__ void __launch_bounds__(NTHREADS, 2)
attn_main(const float* __restrict__ ref,
          const float* __restrict__ Wr_b,
          const float* __restrict__ value,
          float* __restrict__ out_r,
          float* __restrict__ out_logits)
{
    extern __shared__ float sm[];
    const int tid    = threadIdx.x;
    const int lane   = tid & 31;
    const int warp   = tid >> 5;
    const int warp_s = warp & 3;
    const int warp_e = warp >> 2;
    const int b  = blockIdx.y;
    const int s0 = blockIdx.x * BLK_S;
    const int lin = blockIdx.y * gridDim.x + blockIdx.x;   // dispatch-linear bid

    // ---- phase 0: pipelined conversion ----
    if (lin < DELTA) {                    // wave-1: convert own tile (no wait)
        convert_tile(ref, lin, tid);
        __threadfence();
        __syncthreads();
    }
    if (lin + DELTA < NTILES) {           // produce for CTA lin+DELTA
        convert_tile(ref, lin + DELTA, tid);
        __threadfence();
        __syncthreads();
        if (tid == 0) atomicExch(&g_flags[lin + DELTA], 1);
    }
    if (lin >= DELTA) {                   // consume: wait for our tile
        if (tid == 0)
            while (ldacq(&g_flags[lin]) == 0) __nanosleep(64);
        __syncthreads();
    }

    const __half* aG = g_ref16 + ((size_t)b * S_DIM + s0) * D_DIM;
    float* outr_b = out_r + (size_t)b * D_DIM * S_DIM;

    // ---- prefetch stages 0 and 1 ----
    #pragma unroll
    for (int gp = 0; gp < 2; gp++) {
        __half* sa = reinterpret_cast<__half*>(sm + gp * STG_WORDS);
        uint32_t* sb = reinterpret_cast<uint32_t*>(sm) + gp * STG_WORDS + 4096;
        const __half* asrc = aG + (gp & 7) * 64;
        const uint32_t* bsrc = g_w16 + (size_t)gp * 4096;
        #pragma unroll
        for (int i = 0; i < 4; i++) {
            const int ca = tid + i * 256;
            const int row = ca >> 3, gc = ca & 7;
            cp16(sa + row * 64 + ((gc ^ (row & 7)) << 3),
                 asrc + (size_t)row * D_DIM + gc * 8);
            cp16(sb + ca * 4, bsrc + ca * 4);
        }
        asm volatile("cp.async.commit_group;" ::: "memory");
    }

    // epilogue constants
    for (int i = tid; i < D_DIM; i += NTHREADS) {
        SM_BIAS(i) = Wr_b[i];
        SM_QPB(i)  = g_qpb[b * D_DIM + i];
        SM_V(i)    = value[i];
    }
    if (tid < BLK_S) SM_L(tid) = 0.0f;

    // ldmatrix per-thread selectors (invariant)
    const int lrow  = (lane & 15);
    const int lgsel = (lane >> 4) & 1;

    float acc[2][8][4];
    #pragma unroll
    for (int tm = 0; tm < 2; tm++)
        #pragma unroll
        for (int tn = 0; tn < 8; tn++)
            #pragma unroll
            for (int i = 0; i < 4; i++) acc[tm][tn][i] = 0.f;

    unsigned af[2][2][4];
    uint4    bq[4];

    #pragma unroll 1
    for (int g = 0; g < NMACRO; g++) {
        if (g == NMACRO - 1)
            asm volatile("cp.async.wait_group 0;" ::: "memory");
        else
            asm volatile("cp.async.wait_group 1;" ::: "memory");
        __syncthreads();

        // prefetch stage g+2
        if (g + 2 < NMACRO) {
            const int gp = g + 2;
            const int slot = gp % NSTAGE;
            __half* sa = reinterpret_cast<__half*>(sm + slot * STG_WORDS);
            uint32_t* sb = reinterpret_cast<uint32_t*>(sm) + slot * STG_WORDS + 4096;
            const __half* asrc = aG + (gp & 7) * 64;
            const uint32_t* bsrc = g_w16 + (size_t)gp * 4096;
            #pragma unroll
            for (int i = 0; i < 4; i++) {
                const int ca = tid + i * 256;
                const int row = ca >> 3, gc = ca & 7;
                cp16(sa + row * 64 + ((gc ^ (row & 7)) << 3),
                     asrc + (size_t)row * D_DIM + gc * 8);
                cp16(sb + ca * 4, bsrc + ca * 4);
            }
            asm volatile("cp.async.commit_group;" ::: "memory");
        }

        const int slot = g % NSTAGE;
        const unsigned saddr =
            (unsigned)__cvta_generic_to_shared(sm + slot * STG_WORDS);
        const uint32_t* sb =
            reinterpret_cast<const uint32_t*>(sm) + slot * STG_WORDS + 4096;

        // ldmatrix slice 0 into buffer 0
        #pragma unroll
        for (int tm = 0; tm < 2; tm++) {
            const int r = warp_s * 32 + tm * 16 + lrow;
            const unsigned a = saddr + ((r * 8 + (lgsel ^ (r & 7))) << 4);
            ldm4(af[0][tm][0], af[0][tm][1], af[0][tm][2], af[0][tm][3], a);
        }

        #pragma unroll
        for (int ks = 0; ks < 4; ks++) {
            const int pb = ks & 1;
            const uint32_t* sbk = sb + ks * 1024 + warp_e * 512 + lane * 4;
            #pragma unroll
            for (int j = 0; j < 4; j++)
                bq[j] = *reinterpret_cast<const uint4*>(sbk + j * 128);
            if (ks < 3) {
                const int nb = pb ^ 1;
                const int gc = (ks + 1) * 2 + lgsel;
                #pragma unroll
                for (int tm = 0; tm < 2; tm++) {
                    const int r = warp_s * 32 + tm * 16 + lrow;
                    const unsigned a = saddr + ((r * 8 + (gc ^ (r & 7))) << 4);
                    ldm4(af[nb][tm][0], af[nb][tm][1], af[nb][tm][2], af[nb][tm][3], a);
                }
            }
            #pragma unroll
            for (int tm = 0; tm < 2; tm++)
                #pragma unroll
                for (int tn = 0; tn < 8; tn++) {
                    const unsigned b0 = (tn & 1) ? bq[tn >> 1].z : bq[tn >> 1].x;
                    const unsigned b1 = (tn & 1) ? bq[tn >> 1].w : bq[tn >> 1].y;
                    asm volatile(
                        "mma.sync.aligned.m16n8k16.row.col.f32.f16.f16.f32 "
                        "{%0,%1,%2,%3}, {%4,%5,%6,%7}, {%8,%9}, {%0,%1,%2,%3};"
                        : "+f"(acc[tm][tn][0]), "+f"(acc[tm][tn][1]),
                          "+f"(acc[tm][tn][2]), "+f"(acc[tm][tn][3])
                        : "r"(af[pb][tm][0]), "r"(af[pb][tm][1]),
                          "r"(af[pb][tm][2]), "r"(af[pb][tm][3]),
                          "r"(b0), "r"(b1));
                }
        }

        // -------- epilogue at each ei boundary --------
        if ((g & 7) == 7) {
            const int ei = g >> 3;
            float lp[2][2] = {{0.f, 0.f}, {0.f, 0.f}};
            const int sg0 = s0 + warp_s * 32 + (lane >> 2);
            #pragma unroll
            for (int tm = 0; tm < 2; tm++) {
                const int srow = sg0 + tm * 16;
                #pragma unroll
                for (int tn = 0; tn < 8; tn++) {
                    const int e = ei * 128 + warp_e * 64 + tn * 8 + 2 * (lane & 3);
                    const float b0 = SM_BIAS(e), b1 = SM_BIAS(e + 1);
                    const float a0 = acc[tm][tn][0], a1 = acc[tm][tn][1];
                    const float a2 = acc[tm][tn][2], a3 = acc[tm][tn][3];
                    outr_b[(size_t)e       * S_DIM + srow]     = a0 + b0;
                    outr_b[(size_t)(e + 1) * S_DIM + srow]     = a1 + b1;
                    outr_b[(size_t)e       * S_DIM + srow + 8] = a2 + b0;
                    outr_b[(size_t)(e + 1) * S_DIM + srow + 8] = a3 + b1;
                    const float q0 = SM_QPB(e), q1 = SM_QPB(e + 1);
                    const float v0 = SM_V(e), v1 = SM_V(e + 1);
                    lp[tm][0] += tanha(q0 + a0) * v0 + tanha(q1 + a1) * v1;
                    lp[tm][1] += tanha(q0 + a2) * v0 + tanha(q1 + a3) * v1;
                    acc[tm][tn][0] = 0.f; acc[tm][tn][1] = 0.f;
                    acc[tm][tn][2] = 0.f; acc[tm][tn][3] = 0.f;
                }
            }
            #pragma unroll
            for (int tm = 0; tm < 2; tm++)
                #pragma unroll
                for (int h = 0; h < 2; h++) {
                    float v = lp[tm][h];
                    v += __shfl_xor_sync(0xffffffffu, v, 1);
                    v += __shfl_xor_sync(0xffffffffu, v, 2);
                    if ((lane & 3) == 0)
                        atomicAdd(&SM_L(warp_s * 32 + tm * 16 + h * 8 + (lane >> 2)), v);
                }
        }
    }

    __syncthreads();
    if (tid < BLK_S)
        out_logits[(size_t)b * S_DIM + s0 + tid] = 10.0f * tanha(SM_L(tid));
}

// ---------------------------------------------------------------------------
// launch
// ---------------------------------------------------------------------------
extern "C" void kernel_launch(void* const* d_in, const int* in_sizes, int n_in,
                              void* d_out, int out_size) {
    const float* query = (const float*)d_in[0];
    const float* ref   = (const float*)d_in[1];
    const float* Wq_w  = (const float*)d_in[2];
    const float* Wq_b  = (const float*)d_in[3];
    const float* Wr_w  = (const float*)d_in[4];
    const float* Wr_b  = (const float*)d_in[5];
    const float* value = (const float*)d_in[6];
    (void)in_sizes; (void)n_in; (void)out_size;

    float* out        = (float*)d_out;
    float* out_r      = out;                                   // [B, D, S]
    float* out_logits = out + (size_t)B_DIM * D_DIM * S_DIM;   // [B, S]

    prep_kernel<<<1280, 256>>>(Wr_w, query, Wq_w, Wq_b, Wr_b);

    const size_t smem = SMEM_WORDS * sizeof(float);
    cudaFuncSetAttribute(attn_main, cudaFuncAttributeMaxDynamicSharedMemorySize,
                         (int)smem);
    dim3 grid(S_DIM / BLK_S, B_DIM);
    attn_main<<<grid, NTHREADS, smem>>>(ref, Wr_b, value, out_r, out_logits);
}

// round 11
// speedup vs baseline: 1.6093x; 1.0253x over previous
#include <cuda_runtime.h>
#include <cuda_fp16.h>
#include <cstdint>
#include <math.h>

#define B_DIM 64
#define S_DIM 2048
#define D_DIM 512

#define BLK_S 128
#define NTHREADS 256
#define NMACRO 32            // 4 ei * 8 kt (k-tile = 64)
#define NSTAGE 3
#define STG_WORDS 8192       // A 4096 words (8192 fp16) + B 4096 words
#define CONST_OFF (NSTAGE * STG_WORDS)          // 24576
#define SMEM_WORDS (CONST_OFF + 1664)           // 104960 B -> 2 CTAs/SM

#define NCHUNK 4
#define B_CHUNK (B_DIM / NCHUNK)                // 16 batches per chunk

// scratch (no device mallocs; __device__ globals are the sanctioned path)
__device__ __half   g_ref16[(size_t)B_DIM * S_DIM * D_DIM];   // fp16 ref
__device__ uint32_t g_w16[NMACRO * 4096];                     // W fp16, fragment-ordered
__device__ float    g_qpb[B_DIM * D_DIM];                     // q + Wq_b + Wr_b

// ---------------------------------------------------------------------------
// prep: [0,256): W -> fragment-ordered fp16 pairs.  [256,1280): q projection.
// ---------------------------------------------------------------------------
__global__ void prep_kernel(const float* __restrict__ Wr_w,
                            const float* __restrict__ query,
                            const float* __restrict__ Wq_w,
                            const float* __restrict__ Wq_b,
                            const float* __restrict__ Wr_b) {
    if (blockIdx.x < 256) {
        int o = blockIdx.x * 256 + threadIdx.x;
        #pragma unroll
        for (int it = 0; it < 2; it++, o += 65536) {
            const int g = o >> 12, rem = o & 4095;
            const int c = rem >> 2, w = rem & 3;
            const int lane = c & 31, t = c >> 5;
            const int j = t & 3, we = (t >> 2) & 1, ks = t >> 3;
            const int ei = g >> 3, kt = g & 7;
            const int tn = j * 2 + (w >> 1);
            const int e = ei * 128 + we * 64 + tn * 8 + (lane >> 2);
            const int k = kt * 64 + ks * 16 + 2 * (lane & 3) + (w & 1) * 8;
            __half2 h = __floats2half2_rn(Wr_w[e * D_DIM + k], Wr_w[e * D_DIM + k + 1]);
            g_w16[o] = *reinterpret_cast<uint32_t*>(&h);
        }
    } else {
        __shared__ float qs[D_DIM];
        const int id2 = blockIdx.x - 256;
        const int b = id2 & 63;
        const int eblk = id2 >> 6;
        const int tid = threadIdx.x, lane = tid & 31, w = tid >> 5;
        for (int i = tid; i < D_DIM; i += 256) qs[i] = query[(size_t)b * D_DIM + i];
        __syncthreads();
        const int e0 = eblk * 32 + w * 4;
        #pragma unroll
        for (int k = 0; k < 4; k++) {
            const int e = e0 + k;
            const float* wr = Wq_w + (size_t)e * D_DIM;
            float s = 0.f;
            #pragma unroll
            for (int d = lane; d < D_DIM; d += 32) s += qs[d] * wr[d];
            #pragma unroll
            for (int o = 16; o; o >>= 1) s += __shfl_xor_sync(0xffffffffu, s, o);
            if (lane == 0) g_qpb[b * D_DIM + e] = s + Wq_b[e] + Wr_b[e];
        }
    }
}

// ---------------------------------------------------------------------------
// conv_chunk: fp32 -> fp16 for batches [b0, b0 + B_CHUNK)
// ---------------------------------------------------------------------------
__global__ void conv_chunk(const float* __restrict__ ref, int b0) {
    const size_t base4 = (size_t)b0 * S_DIM * D_DIM / 4;
    const size_t i4 = base4 + (size_t)blockIdx.x * 256 + threadIdx.x;
    const float4 v = reinterpret_cast<const float4*>(ref)[i4];
    __half2 h0 = __floats2half2_rn(v.x, v.y);
    __half2 h1 = __floats2half2_rn(v.z, v.w);
    uint2 o;
    o.x = *reinterpret_cast<uint32_t*>(&h0);
    o.y = *reinterpret_cast<uint32_t*>(&h1);
    reinterpret_cast<uint2*>(g_ref16)[i4] = o;
}

// ---------------------------------------------------------------------------
// helpers
// ---------------------------------------------------------------------------
__device__ __forceinline__ void cp16(void* dst, const void* src) {
    unsigned s = (unsigned)__cvta_generic_to_shared(dst);
    asm volatile("cp.async.cg.shared.global [%0], [%1], 16;"
                 :: "r"(s), "l"(src) : "memory");
}
__device__ __forceinline__ float tanha(float x) {
    float y;
    asm("tanh.approx.f32 %0, %1;" : "=f"(y) : "f"(x));
    return y;
}
__device__ __forceinline__ void ldm4(unsigned& r0, unsigned& r1, unsigned& r2,
                                     unsigned& r3, unsigned addr) {
    asm volatile("ldmatrix.sync.aligned.m8n8.x4.shared.b16 {%0,%1,%2,%3}, [%4];"
                 : "=r"(r0), "=r"(r1), "=r"(r2), "=r"(r3) : "r"(addr));
}

#define SM_BIAS(i) sm[CONST_OFF + (i)]
#define SM_QPB(i)  sm[CONST_OFF + 512 + (i)]
#define SM_V(i)    sm[CONST_OFF + 1024 + (i)]
#define SM_L(i)    sm[CONST_OFF + 1536 + (i)]

// ---------------------------------------------------------------------------
// main: fp16 m16n8k16 HMMA, flattened 32-iteration, 3-stage cp.async ring
// (identical to the 196.6us R6 kernel; b offset for chunked launch)
// ---------------------------------------------------------------------------
__global__ void __launch_bounds__(NTHREADS, 2)
attn_main(const float* __restrict__ Wr_b,
          const float* __restrict__ value,
          float* __restrict__ out_r,
          float* __restrict__ out_logits,
          int b0)
{
    extern __shared__ float sm[];
    const int tid    = threadIdx.x;
    const int lane   = tid & 31;
    const int warp   = tid >> 5;
    const int warp_s = warp & 3;
    const int warp_e = warp >> 2;
    const int b  = b0 + blockIdx.y;
    const int s0 = blockIdx.x * BLK_S;

    const __half* aG = g_ref16 + ((size_t)b * S_DIM + s0) * D_DIM;
    float* outr_b = out_r + (size_t)b * D_DIM * S_DIM;

    // ---- prefetch stages 0 and 1 ----
    #pragma unroll
    for (int gp = 0; gp < 2; gp++) {
        __half* sa = reinterpret_cast<__half*>(sm + gp * STG_WORDS);
        uint32_t* sb = reinterpret_cast<uint32_t*>(sm) + gp * STG_WORDS + 4096;
        const __half* asrc = aG + (gp & 7) * 64;
        const uint32_t* bsrc = g_w16 + (size_t)gp * 4096;
        #pragma unroll
        for (int i = 0; i < 4; i++) {
            const int ca = tid + i * 256;
            const int row = ca >> 3, gc = ca & 7;
            cp16(sa + row * 64 + ((gc ^ (row & 7)) << 3),
                 asrc + (size_t)row * D_DIM + gc * 8);
            cp16(sb + ca * 4, bsrc + ca * 4);
        }
        asm volatile("cp.async.commit_group;" ::: "memory");
    }

    // epilogue constants
    for (int i = tid; i < D_DIM; i += NTHREADS) {
        SM_BIAS(i) = Wr_b[i];
        SM_QPB(i)  = g_qpb[b * D_DIM + i];
        SM_V(i)    = value[i];
    }
    if (tid < BLK_S) SM_L(tid) = 0.0f;

    // ldmatrix per-thread selectors (invariant)
    const int lrow  = (lane & 15);
    const int lgsel = (lane >> 4) & 1;

    float acc[2][8][4];
    #pragma unroll
    for (int tm = 0; tm < 2; tm++)
        #pragma unroll
        for (int tn = 0; tn < 8; tn++)
            #pragma unroll
            for (int i = 0; i < 4; i++) acc[tm][tn][i] = 0.f;

    unsigned af[2][2][4];
    uint4    bq[4];

    #pragma unroll 1
    for (int g = 0; g < NMACRO; g++) {
        if (g == NMACRO - 1)
            asm volatile("cp.async.wait_group 0;" ::: "memory");
        else
            asm volatile("cp.async.wait_group 1;" ::: "memory");
        __syncthreads();

        // prefetch stage g+2
        if (g + 2 < NMACRO) {
            const int gp = g + 2;
            const int slot = gp % NSTAGE;
            __half* sa = reinterpret_cast<__half*>(sm + slot * STG_WORDS);
            uint32_t* sb = reinterpret_cast<uint32_t*>(sm) + slot * STG_WORDS + 4096;
            const __half* asrc = aG + (gp & 7) * 64;
            const uint32_t* bsrc = g_w16 + (size_t)gp * 4096;
            #pragma unroll
            for (int i = 0; i < 4; i++) {
                const int ca = tid + i * 256;
                const int row = ca >> 3, gc = ca & 7;
                cp16(sa + row * 64 + ((gc ^ (row & 7)) << 3),
                     asrc + (size_t)row * D_DIM + gc * 8);
                cp16(sb + ca * 4, bsrc + ca * 4);
            }
            asm volatile("cp.async.commit_group;" ::: "memory");
        }

        const int slot = g % NSTAGE;
        const unsigned saddr =
            (unsigned)__cvta_generic_to_shared(sm + slot * STG_WORDS);
        const uint32_t* sb =
            reinterpret_cast<const uint32_t*>(sm) + slot * STG_WORDS + 4096;

        // ldmatrix slice 0 into buffer 0
        #pragma unroll
        for (int tm = 0; tm < 2; tm++) {
            const int r = warp_s * 32 + tm * 16 + lrow;
            const unsigned a = saddr + ((r * 8 + (lgsel ^ (r & 7))) << 4);
            ldm4(af[0][tm][0], af[0][tm][1], af[0][tm][2], af[0][tm][3], a);
        }

        #pragma unroll
        for (int ks = 0; ks < 4; ks++) {
            const int pb = ks & 1;
            const uint32_t* sbk = sb + ks * 1024 + warp_e * 512 + lane * 4;
            #pragma unroll
            for (int j = 0; j < 4; j++)
                bq[j] = *reinterpret_cast<const uint4*>(sbk + j * 128);
            if (ks < 3) {
                const int nb = pb ^ 1;
                const int gc = (ks + 1) * 2 + lgsel;
                #pragma unroll
                for (int tm = 0; tm < 2; tm++) {
                    const int r = warp_s * 32 + tm * 16 + lrow;
                    const unsigned a = saddr + ((r * 8 + (gc ^ (r & 7))) << 4);
                    ldm4(af[nb][tm][0], af[nb][tm][1], af[nb][tm][2], af[nb][tm][3], a);
                }
            }
            #pragma unroll
            for (int tm = 0; tm < 2; tm++)
                #pragma unroll
                for (int tn = 0; tn < 8; tn++) {
                    const unsigned b0f = (tn & 1) ? bq[tn >> 1].z : bq[tn >> 1].x;
                    const unsigned b1f = (tn & 1) ? bq[tn >> 1].w : bq[tn >> 1].y;
                    asm volatile(
                        "mma.sync.aligned.m16n8k16.row.col.f32.f16.f16.f32 "
                        "{%0,%1,%2,%3}, {%4,%5,%6,%7}, {%8,%9}, {%0,%1,%2,%3};"
                        : "+f"(acc[tm][tn][0]), "+f"(acc[tm][tn][1]),
                          "+f"(acc[tm][tn][2]), "+f"(acc[tm][tn][3])
                        : "r"(af[pb][tm][0]), "r"(af[pb][tm][1]),
                          "r"(af[pb][tm][2]), "r"(af[pb][tm][3]),
                          "r"(b0f), "r"(b1f));
                }
        }

        // -------- epilogue at each ei boundary --------
        if ((g & 7) == 7) {
            const int ei = g >> 3;
            float lp[2][2] = {{0.f, 0.f}, {0.f, 0.f}};
            const int sg0 = s0 + warp_s * 32 + (lane >> 2);
            #pragma unroll
            for (int tm = 0; tm < 2; tm++) {
                const int srow = sg0 + tm * 16;
                #pragma unroll
                for (int tn = 0; tn < 8; tn++) {
                    const int e = ei * 128 + warp_e * 64 + tn * 8 + 2 * (lane & 3);
                    const float b0v = SM_BIAS(e), b1v = SM_BIAS(e + 1);
                    const float a0 = acc[tm][tn][0], a1 = acc[tm][tn][1];
                    const float a2 = acc[tm][tn][2], a3 = acc[tm][tn][3];
                    outr_b[(size_t)e       * S_DIM + srow]     = a0 + b0v;
                    outr_b[(size_t)(e + 1) * S_DIM + srow]     = a1 + b1v;
                    outr_b[(size_t)e       * S_DIM + srow + 8] = a2 + b0v;
                    outr_b[(size_t)(e + 1) * S_DIM + srow + 8] = a3 + b1v;
                    const float q0 = SM_QPB(e), q1 = SM_QPB(e + 1);
                    const float v0 = SM_V(e), v1 = SM_V(e + 1);
                    lp[tm][0] += tanha(q0 + a0) * v0 + tanha(q1 + a1) * v1;
                    lp[tm][1] += tanha(q0 + a2) * v0 + tanha(q1 + a3) * v1;
                    acc[tm][tn][0] = 0.f; acc[tm][tn][1] = 0.f;
                    acc[tm][tn][2] = 0.f; acc[tm][tn][3] = 0.f;
                }
            }
            #pragma unroll
            for (int tm = 0; tm < 2; tm++)
                #pragma unroll
                for (int h = 0; h < 2; h++) {
                    float v = lp[tm][h];
                    v += __shfl_xor_sync(0xffffffffu, v, 1);
                    v += __shfl_xor_sync(0xffffffffu, v, 2);
                    if ((lane & 3) == 0)
                        atomicAdd(&SM_L(warp_s * 32 + tm * 16 + h * 8 + (lane >> 2)), v);
                }
        }
    }

    __syncthreads();
    if (tid < BLK_S)
        out_logits[(size_t)b * S_DIM + s0 + tid] = 10.0f * tanha(SM_L(tid));
}

// ---------------------------------------------------------------------------
// launch: fork/join stream DAG so conversion chunk i+1 overlaps main chunk i
// ---------------------------------------------------------------------------
extern "C" void kernel_launch(void* const* d_in, const int* in_sizes, int n_in,
                              void* d_out, int out_size) {
    const float* query = (const float*)d_in[0];
    const float* ref   = (const float*)d_in[1];
    const float* Wq_w  = (const float*)d_in[2];
    const float* Wq_b  = (const float*)d_in[3];
    const float* Wr_w  = (const float*)d_in[4];
    const float* Wr_b  = (const float*)d_in[5];
    const float* value = (const float*)d_in[6];
    (void)in_sizes; (void)n_in; (void)out_size;

    float* out        = (float*)d_out;
    float* out_r      = out;                                   // [B, D, S]
    float* out_logits = out + (size_t)B_DIM * D_DIM * S_DIM;   // [B, S]

    // one-time infra (created on the uncaptured correctness call)
    static cudaStream_t sC = nullptr;   // conversion stream
    static cudaStream_t sB = nullptr;   // second main stream
    static cudaEvent_t evFork, evPrep, evC[NCHUNK], evB;
    static bool smem_set = false;
    if (!sC) {
        cudaStreamCreateWithFlags(&sC, cudaStreamNonBlocking);
        cudaStreamCreateWithFlags(&sB, cudaStreamNonBlocking);
        cudaEventCreateWithFlags(&evFork, cudaEventDisableTiming);
        cudaEventCreateWithFlags(&evPrep, cudaEventDisableTiming);
        for (int i = 0; i < NCHUNK; i++)
            cudaEventCreateWithFlags(&evC[i], cudaEventDisableTiming);
        cudaEventCreateWithFlags(&evB, cudaEventDisableTiming);
    }
    if (!smem_set) {
        cudaFuncSetAttribute(attn_main, cudaFuncAttributeMaxDynamicSharedMemorySize,
                             (int)(SMEM_WORDS * sizeof(float)));
        smem_set = true;
    }
    const size_t smem = SMEM_WORDS * sizeof(float);
    const int conv_blocks = B_CHUNK * S_DIM * D_DIM / 4 / 256;   // 16384

    // fork conversion stream from origin
    cudaEventRecord(evFork, 0);
    cudaStreamWaitEvent(sC, evFork, 0);
    for (int i = 0; i < NCHUNK; i++) {
        conv_chunk<<<conv_blocks, 256, 0, sC>>>(ref, i * B_CHUNK);
        cudaEventRecord(evC[i], sC);
    }

    // prep on origin stream
    prep_kernel<<<1280, 256>>>(Wr_w, query, Wq_w, Wq_b, Wr_b);
    cudaEventRecord(evPrep, 0);

    dim3 grid(S_DIM / BLK_S, B_CHUNK);

    // main chunks 0,2 on origin; 1,3 on sB (pairs run concurrently)
    cudaStreamWaitEvent(0, evC[0], 0);
    attn_main<<<grid, NTHREADS, smem>>>(Wr_b, value, out_r, out_logits, 0 * B_CHUNK);

    cudaStreamWaitEvent(sB, evPrep, 0);
    cudaStreamWaitEvent(sB, evC[1], 0);
    attn_main<<<grid, NTHREADS, smem, sB>>>(Wr_b, value, out_r, out_logits, 1 * B_CHUNK);

    cudaStreamWaitEvent(0, evC[2], 0);
    attn_main<<<grid, NTHREADS, smem>>>(Wr_b, value, out_r, out_logits, 2 * B_CHUNK);

    cudaStreamWaitEvent(sB, evC[3], 0);
    attn_main<<<grid, NTHREADS, smem, sB>>>(Wr_b, value, out_r, out_logits, 3 * B_CHUNK);
    cudaEventRecord(evB, sB);

    // join everything back to origin stream
    cudaStreamWaitEvent(0, evB, 0);
}

// round 12
// speedup vs baseline: 1.7162x; 1.0664x over previous
#include <cuda_runtime.h>
#include <cuda_fp16.h>
#include <cstdint>
#include <math.h>

#define B_DIM 64
#define S_DIM 2048
#define D_DIM 512

#define BLK_S 128
#define NTHREADS 256
#define NMACRO 32            // 4 ei * 8 kt (k-tile = 64)
#define STG_BYTES 49152      // A fp32 32KB + B fp16 16KB
#define CONST_OFF 24576      // words (= 2 * STG_BYTES / 4)
#define SMEM_WORDS (CONST_OFF + 1664)    // 104960 B -> 2 CTAs/SM

// scratch (no device mallocs; __device__ globals are the sanctioned path)
__device__ uint32_t g_w16[NMACRO * 4096];   // W fp16, fragment-ordered
__device__ float    g_qpb[B_DIM * D_DIM];   // q + Wq_b + Wr_b

// ---------------------------------------------------------------------------
// prep: [0,256): W -> fragment-ordered fp16 pairs.  [256,1280): q projection.
// ---------------------------------------------------------------------------
__global__ void prep_kernel(const float* __restrict__ Wr_w,
                            const float* __restrict__ query,
                            const float* __restrict__ Wq_w,
                            const float* __restrict__ Wq_b,
                            const float* __restrict__ Wr_b) {
    if (blockIdx.x < 256) {
        int o = blockIdx.x * 256 + threadIdx.x;
        #pragma unroll
        for (int it = 0; it < 2; it++, o += 65536) {
            const int g = o >> 12, rem = o & 4095;
            const int c = rem >> 2, w = rem & 3;
            const int lane = c & 31, t = c >> 5;
            const int j = t & 3, we = (t >> 2) & 1, ks = t >> 3;
            const int ei = g >> 3, kt = g & 7;
            const int tn = j * 2 + (w >> 1);
            const int e = ei * 128 + we * 64 + tn * 8 + (lane >> 2);
            const int k = kt * 64 + ks * 16 + 2 * (lane & 3) + (w & 1) * 8;
            __half2 h = __floats2half2_rn(Wr_w[e * D_DIM + k], Wr_w[e * D_DIM + k + 1]);
            g_w16[o] = *reinterpret_cast<uint32_t*>(&h);
        }
    } else {
        __shared__ float qs[D_DIM];
        const int id2 = blockIdx.x - 256;
        const int b = id2 & 63;
        const int eblk = id2 >> 6;
        const int tid = threadIdx.x, lane = tid & 31, w = tid >> 5;
        for (int i = tid; i < D_DIM; i += 256) qs[i] = query[(size_t)b * D_DIM + i];
        __syncthreads();
        const int e0 = eblk * 32 + w * 4;
        #pragma unroll
        for (int k = 0; k < 4; k++) {
            const int e = e0 + k;
            const float* wr = Wq_w + (size_t)e * D_DIM;
            float s = 0.f;
            #pragma unroll
            for (int d = lane; d < D_DIM; d += 32) s += qs[d] * wr[d];
            #pragma unroll
            for (int o = 16; o; o >>= 1) s += __shfl_xor_sync(0xffffffffu, s, o);
            if (lane == 0) g_qpb[b * D_DIM + e] = s + Wq_b[e] + Wr_b[e];
        }
    }
}

// ---------------------------------------------------------------------------
// helpers
// ---------------------------------------------------------------------------
__device__ __forceinline__ void cp16(void* dst, const void* src) {
    unsigned s = (unsigned)__cvta_generic_to_shared(dst);
    asm volatile("cp.async.cg.shared.global [%0], [%1], 16;"
                 :: "r"(s), "l"(src) : "memory");
}
__device__ __forceinline__ float tanha(float x) {
    float y;
    asm("tanh.approx.f32 %0, %1;" : "=f"(y) : "f"(x));
    return y;
}
// pack two fp32 (bit patterns) into fp16x2 with rn
__device__ __forceinline__ unsigned cvt_pair(uint2 t) {
    __half2 h = __floats2half2_rn(__uint_as_float(t.x), __uint_as_float(t.y));
    return *reinterpret_cast<unsigned*>(&h);
}

#define SM_BIAS(i) sm[CONST_OFF + (i)]
#define SM_QPB(i)  sm[CONST_OFF + 512 + (i)]
#define SM_V(i)    sm[CONST_OFF + 1024 + (i)]
#define SM_L(i)    sm[CONST_OFF + 1536 + (i)]

// ---------------------------------------------------------------------------
// main: fp16 m16n8k16 HMMA. A staged as fp32 (cp.async direct from ref),
// converted to fp16 in the fragment path (LDS.64 + cvt.f16x2). B fp16 staged.
// 2-stage ring, one barrier per macro.
// A stage: uint2[128][32], pair pg at pos = pg ^ ((row&3)<<2)  (16B-unit XOR)
// ---------------------------------------------------------------------------
__global__ void __launch_bounds__(NTHREADS, 2)
attn_main(const float* __restrict__ ref,
          const float* __restrict__ Wr_b,
          const float* __restrict__ value,
          float* __restrict__ out_r,
          float* __restrict__ out_logits)
{
    extern __shared__ float sm[];
    char* smc = reinterpret_cast<char*>(sm);
    const int tid    = threadIdx.x;
    const int lane   = tid & 31;
    const int warp   = tid >> 5;
    const int warp_s = warp & 3;
    const int warp_e = warp >> 2;
    const int b  = blockIdx.y;
    const int s0 = blockIdx.x * BLK_S;

    const float* aG32 = ref + ((size_t)b * S_DIM + s0) * D_DIM;
    float* outr_b = out_r + (size_t)b * D_DIM * S_DIM;

    // per-thread A write coordinates: 8 chunks of 16B (4 fp32)
    // chunk c = tid + i*256 : row = c>>4, unit u = c&15, pos u' = u ^ ((row&3)<<1)
    // prefetch one macro (A 32KB fp32 + B 16KB fp16) into slot
    auto prefetch = [&](int g, int slot) {
        uint2* sa = reinterpret_cast<uint2*>(smc + slot * STG_BYTES);
        uint32_t* sb = reinterpret_cast<uint32_t*>(smc + slot * STG_BYTES + 32768);
        const float* asrc = aG32 + (g & 7) * 64;
        const uint32_t* bsrc = g_w16 + (size_t)g * 4096;
        #pragma unroll
        for (int i = 0; i < 8; i++) {
            const int c = tid + i * 256;
            const int row = c >> 4, u = c & 15;
            const int up = u ^ ((row & 3) << 1);
            cp16(sa + row * 32 + up * 2, asrc + (size_t)row * D_DIM + u * 4);
        }
        #pragma unroll
        for (int i = 0; i < 4; i++)
            cp16(sb + (tid + i * 256) * 4, bsrc + (tid + i * 256) * 4);
        asm volatile("cp.async.commit_group;" ::: "memory");
    };

    // prologue: stage 0
    prefetch(0, 0);

    // epilogue constants
    for (int i = tid; i < D_DIM; i += NTHREADS) {
        SM_BIAS(i) = Wr_b[i];
        SM_QPB(i)  = g_qpb[b * D_DIM + i];
        SM_V(i)    = value[i];
    }
    if (tid < BLK_S) SM_L(tid) = 0.0f;

    const int rbase = warp_s * 32 + (lane >> 2);   // A row base (tm*16 added)
    const int plo   = lane & 3;                    // pair-lane within slice

    float acc[2][8][4];
    #pragma unroll
    for (int tm = 0; tm < 2; tm++)
        #pragma unroll
        for (int tn = 0; tn < 8; tn++)
            #pragma unroll
            for (int i = 0; i < 4; i++) acc[tm][tn][i] = 0.f;

    unsigned af[2][2][4];
    uint4    bq[4];

    #pragma unroll 1
    for (int g = 0; g < NMACRO; g++) {
        asm volatile("cp.async.wait_group 0;" ::: "memory");
        __syncthreads();

        if (g + 1 < NMACRO) prefetch(g + 1, (g + 1) & 1);

        const int slot = g & 1;
        const uint2* sa = reinterpret_cast<const uint2*>(smc + slot * STG_BYTES);
        const uint32_t* sb =
            reinterpret_cast<const uint32_t*>(smc + slot * STG_BYTES + 32768);

        // A fragment loader: LDS.64 fp32 pair + cvt -> fp16x2
        auto loadA = [&](int buf, int ks) {
            const int p = ks * 8 + plo;
            #pragma unroll
            for (int tm = 0; tm < 2; tm++) {
                const int r0 = rbase + tm * 16;
                const int sw = (r0 & 3) << 2;      // (r0+8)&3 == r0&3
                af[buf][tm][0] = cvt_pair(sa[ r0      * 32 + ( p      ^ sw)]);
                af[buf][tm][1] = cvt_pair(sa[(r0 + 8) * 32 + ( p      ^ sw)]);
                af[buf][tm][2] = cvt_pair(sa[ r0      * 32 + ((p + 4) ^ sw)]);
                af[buf][tm][3] = cvt_pair(sa[(r0 + 8) * 32 + ((p + 4) ^ sw)]);
            }
        };

        loadA(0, 0);

        #pragma unroll
        for (int ks = 0; ks < 4; ks++) {
            const int pb = ks & 1;
            const uint32_t* sbk = sb + ks * 1024 + warp_e * 512 + lane * 4;
            #pragma unroll
            for (int j = 0; j < 4; j++)
                bq[j] = *reinterpret_cast<const uint4*>(sbk + j * 128);
            if (ks < 3) loadA(pb ^ 1, ks + 1);
            #pragma unroll
            for (int tm = 0; tm < 2; tm++)
                #pragma unroll
                for (int tn = 0; tn < 8; tn++) {
                    const unsigned b0f = (tn & 1) ? bq[tn >> 1].z : bq[tn >> 1].x;
                    const unsigned b1f = (tn & 1) ? bq[tn >> 1].w : bq[tn >> 1].y;
                    asm volatile(
                        "mma.sync.aligned.m16n8k16.row.col.f32.f16.f16.f32 "
                        "{%0,%1,%2,%3}, {%4,%5,%6,%7}, {%8,%9}, {%0,%1,%2,%3};"
                        : "+f"(acc[tm][tn][0]), "+f"(acc[tm][tn][1]),
                          "+f"(acc[tm][tn][2]), "+f"(acc[tm][tn][3])
                        : "r"(af[pb][tm][0]), "r"(af[pb][tm][1]),
                          "r"(af[pb][tm][2]), "r"(af[pb][tm][3]),
                          "r"(b0f), "r"(b1f));
                }
        }

        // -------- epilogue at each ei boundary --------
        if ((g & 7) == 7) {
            const int ei = g >> 3;
            float lp[2][2] = {{0.f, 0.f}, {0.f, 0.f}};
            const int sg0 = s0 + warp_s * 32 + (lane >> 2);
            #pragma unroll
            for (int tm = 0; tm < 2; tm++) {
                const int srow = sg0 + tm * 16;
                #pragma unroll
                for (int tn = 0; tn < 8; tn++) {
                    const int e = ei * 128 + warp_e * 64 + tn * 8 + 2 * (lane & 3);
                    const float b0v = SM_BIAS(e), b1v = SM_BIAS(e + 1);
                    const float a0 = acc[tm][tn][0], a1 = acc[tm][tn][1];
                    const float a2 = acc[tm][tn][2], a3 = acc[tm][tn][3];
                    outr_b[(size_t)e       * S_DIM + srow]     = a0 + b0v;
                    outr_b[(size_t)(e + 1) * S_DIM + srow]     = a1 + b1v;
                    outr_b[(size_t)e       * S_DIM + srow + 8] = a2 + b0v;
                    outr_b[(size_t)(e + 1) * S_DIM + srow + 8] = a3 + b1v;
                    const float q0 = SM_QPB(e), q1 = SM_QPB(e + 1);
                    const float v0 = SM_V(e), v1 = SM_V(e + 1);
                    lp[tm][0] += tanha(q0 + a0) * v0 + tanha(q1 + a1) * v1;
                    lp[tm][1] += tanha(q0 + a2) * v0 + tanha(q1 + a3) * v1;
                    acc[tm][tn][0] = 0.f; acc[tm][tn][1] = 0.f;
                    acc[tm][tn][2] = 0.f; acc[tm][tn][3] = 0.f;
                }
            }
            #pragma unroll
            for (int tm = 0; tm < 2; tm++)
                #pragma unroll
                for (int h = 0; h < 2; h++) {
                    float v = lp[tm][h];
                    v += __shfl_xor_sync(0xffffffffu, v, 1);
                    v += __shfl_xor_sync(0xffffffffu, v, 2);
                    if ((lane & 3) == 0)
                        atomicAdd(&SM_L(warp_s * 32 + tm * 16 + h * 8 + (lane >> 2)), v);
                }
        }
    }

    __syncthreads();
    if (tid < BLK_S)
        out_logits[(size_t)b * S_DIM + s0 + tid] = 10.0f * tanha(SM_L(tid));
}

// ---------------------------------------------------------------------------
// launch
// ---------------------------------------------------------------------------
extern "C" void kernel_launch(void* const* d_in, const int* in_sizes, int n_in,
                              void* d_out, int out_size) {
    const float* query = (const float*)d_in[0];
    const float* ref   = (const float*)d_in[1];
    const float* Wq_w  = (const float*)d_in[2];
    const float* Wq_b  = (const float*)d_in[3];
    const float* Wr_w  = (const float*)d_in[4];
    const float* Wr_b  = (const float*)d_in[5];
    const float* value = (const float*)d_in[6];
    (void)in_sizes; (void)n_in; (void)out_size;

    float* out        = (float*)d_out;
    float* out_r      = out;                                   // [B, D, S]
    float* out_logits = out + (size_t)B_DIM * D_DIM * S_DIM;   // [B, S]

    prep_kernel<<<1280, 256>>>(Wr_w, query, Wq_w, Wq_b, Wr_b);

    const size_t smem = SMEM_WORDS * sizeof(float);
    cudaFuncSetAttribute(attn_main, cudaFuncAttributeMaxDynamicSharedMemorySize,
                         (int)smem);
    dim3 grid(S_DIM / BLK_S, B_DIM);
    attn_main<<<grid, NTHREADS, smem>>>(ref, Wr_b, value, out_r, out_logits);
}

// round 13
// speedup vs baseline: 1.7455x; 1.0171x over previous
#include <cuda_runtime.h>
#include <cuda_fp16.h>
#include <cstdint>
#include <math.h>

#define B_DIM 64
#define S_DIM 2048
#define D_DIM 512

#define BLK_S 128
#define NTHREADS 256
#define NMACRO 32            // 4 ei * 8 kt (k-tile = 64)
#define STG_BYTES 49152      // A fp32 32KB + B fp16 16KB
#define CONST_OFF 24576      // words (= 2 * STG_BYTES / 4)
#define SMEM_WORDS (CONST_OFF + 1664)    // 104960 B -> 2 CTAs/SM

// scratch (no device mallocs; __device__ globals are the sanctioned path)
__device__ uint32_t g_w16[NMACRO * 4096];   // W fp16, fragment-ordered
__device__ float    g_qpb[B_DIM * D_DIM];   // q + Wq_b + Wr_b

// ---------------------------------------------------------------------------
// prep: [0,256): W -> fragment-ordered fp16 pairs.  [256,1280): q projection.
// ---------------------------------------------------------------------------
__global__ void prep_kernel(const float* __restrict__ Wr_w,
                            const float* __restrict__ query,
                            const float* __restrict__ Wq_w,
                            const float* __restrict__ Wq_b,
                            const float* __restrict__ Wr_b) {
    if (blockIdx.x < 256) {
        int o = blockIdx.x * 256 + threadIdx.x;
        #pragma unroll
        for (int it = 0; it < 2; it++, o += 65536) {
            const int g = o >> 12, rem = o & 4095;
            const int c = rem >> 2, w = rem & 3;
            const int lane = c & 31, t = c >> 5;
            const int j = t & 3, we = (t >> 2) & 1, ks = t >> 3;
            const int ei = g >> 3, kt = g & 7;
            const int tn = j * 2 + (w >> 1);
            const int e = ei * 128 + we * 64 + tn * 8 + (lane >> 2);
            const int k = kt * 64 + ks * 16 + 2 * (lane & 3) + (w & 1) * 8;
            __half2 h = __floats2half2_rn(Wr_w[e * D_DIM + k], Wr_w[e * D_DIM + k + 1]);
            g_w16[o] = *reinterpret_cast<uint32_t*>(&h);
        }
    } else {
        __shared__ float qs[D_DIM];
        const int id2 = blockIdx.x - 256;
        const int b = id2 & 63;
        const int eblk = id2 >> 6;
        const int tid = threadIdx.x, lane = tid & 31, w = tid >> 5;
        for (int i = tid; i < D_DIM; i += 256) qs[i] = query[(size_t)b * D_DIM + i];
        __syncthreads();
        const int e0 = eblk * 32 + w * 4;
        #pragma unroll
        for (int k = 0; k < 4; k++) {
            const int e = e0 + k;
            const float* wr = Wq_w + (size_t)e * D_DIM;
            float s = 0.f;
            #pragma unroll
            for (int d = lane; d < D_DIM; d += 32) s += qs[d] * wr[d];
            #pragma unroll
            for (int o = 16; o; o >>= 1) s += __shfl_xor_sync(0xffffffffu, s, o);
            if (lane == 0) g_qpb[b * D_DIM + e] = s + Wq_b[e] + Wr_b[e];
        }
    }
}

// ---------------------------------------------------------------------------
// helpers
// ---------------------------------------------------------------------------
__device__ __forceinline__ void cp16(void* dst, const void* src) {
    unsigned s = (unsigned)__cvta_generic_to_shared(dst);
    asm volatile("cp.async.cg.shared.global [%0], [%1], 16;"
                 :: "r"(s), "l"(src) : "memory");
}
__device__ __forceinline__ float tanha(float x) {
    float y;
    asm("tanh.approx.f32 %0, %1;" : "=f"(y) : "f"(x));
    return y;
}
__device__ __forceinline__ unsigned cvt_pair(uint2 t) {
    __half2 h = __floats2half2_rn(__uint_as_float(t.x), __uint_as_float(t.y));
    return *reinterpret_cast<unsigned*>(&h);
}

#define SM_BIAS(i) sm[CONST_OFF + (i)]
#define SM_QPB(i)  sm[CONST_OFF + 512 + (i)]
#define SM_V(i)    sm[CONST_OFF + 1024 + (i)]
#define SM_L(i)    sm[CONST_OFF + 1536 + (i)]

// ---------------------------------------------------------------------------
// main: fp16 m16n8k16 HMMA. A staged fp32 (cp.async direct), cvt in fragment
// path. B fp16 staged. 2-stage ring, 1 barrier/macro. Half-slice-pipelined
// B fragments (every LDS covered by ~8 MMAs).
// ---------------------------------------------------------------------------
__global__ void __launch_bounds__(NTHREADS, 2)
attn_main(const float* __restrict__ ref,
          const float* __restrict__ Wr_b,
          const float* __restrict__ value,
          float* __restrict__ out_r,
          float* __restrict__ out_logits)
{
    extern __shared__ float sm[];
    char* smc = reinterpret_cast<char*>(sm);
    const int tid    = threadIdx.x;
    const int lane   = tid & 31;
    const int warp   = tid >> 5;
    const int warp_s = warp & 3;
    const int warp_e = warp >> 2;
    const int b  = blockIdx.y;
    const int s0 = blockIdx.x * BLK_S;

    const float* aG32 = ref + ((size_t)b * S_DIM + s0) * D_DIM;
    float* outr_b = out_r + (size_t)b * D_DIM * S_DIM;

    auto prefetch = [&](int g, int slot) {
        uint2* sa = reinterpret_cast<uint2*>(smc + slot * STG_BYTES);
        uint32_t* sb = reinterpret_cast<uint32_t*>(smc + slot * STG_BYTES + 32768);
        const float* asrc = aG32 + (g & 7) * 64;
        const uint32_t* bsrc = g_w16 + (size_t)g * 4096;
        #pragma unroll
        for (int i = 0; i < 8; i++) {
            const int c = tid + i * 256;
            const int row = c >> 4, u = c & 15;
            const int up = u ^ ((row & 3) << 1);
            cp16(sa + row * 32 + up * 2, asrc + (size_t)row * D_DIM + u * 4);
        }
        #pragma unroll
        for (int i = 0; i < 4; i++)
            cp16(sb + (tid + i * 256) * 4, bsrc + (tid + i * 256) * 4);
        asm volatile("cp.async.commit_group;" ::: "memory");
    };

    prefetch(0, 0);

    // epilogue constants
    for (int i = tid; i < D_DIM; i += NTHREADS) {
        SM_BIAS(i) = Wr_b[i];
        SM_QPB(i)  = g_qpb[b * D_DIM + i];
        SM_V(i)    = value[i];
    }
    if (tid < BLK_S) SM_L(tid) = 0.0f;

    const int rbase = warp_s * 32 + (lane >> 2);
    const int plo   = lane & 3;
    const int bbase = warp_e * 512 + lane * 4;   // words within B ks-block

    float acc[2][8][4];
    #pragma unroll
    for (int tm = 0; tm < 2; tm++)
        #pragma unroll
        for (int tn = 0; tn < 8; tn++)
            #pragma unroll
            for (int i = 0; i < 4; i++) acc[tm][tn][i] = 0.f;

    unsigned af[2][2][4];
    uint4    bq[2][2];    // ping-pong half-slice B fragments

    #pragma unroll 1
    for (int g = 0; g < NMACRO; g++) {
        asm volatile("cp.async.wait_group 0;" ::: "memory");
        __syncthreads();

        if (g + 1 < NMACRO) prefetch(g + 1, (g + 1) & 1);

        const int slot = g & 1;
        const uint2* sa = reinterpret_cast<const uint2*>(smc + slot * STG_BYTES);
        const uint32_t* sb =
            reinterpret_cast<const uint32_t*>(smc + slot * STG_BYTES + 32768);

        auto loadA = [&](int buf, int ks) {
            const int p = ks * 8 + plo;
            #pragma unroll
            for (int tm = 0; tm < 2; tm++) {
                const int r0 = rbase + tm * 16;
                const int sw = (r0 & 3) << 2;
                af[buf][tm][0] = cvt_pair(sa[ r0      * 32 + ( p      ^ sw)]);
                af[buf][tm][1] = cvt_pair(sa[(r0 + 8) * 32 + ( p      ^ sw)]);
                af[buf][tm][2] = cvt_pair(sa[ r0      * 32 + ((p + 4) ^ sw)]);
                af[buf][tm][3] = cvt_pair(sa[(r0 + 8) * 32 + ((p + 4) ^ sw)]);
            }
        };
        // half-slice B loader: i = ks*2 + half
        auto loadB = [&](int buf, int i) {
            const uint32_t* p = sb + (i >> 1) * 1024 + (i & 1) * 256 + bbase;
            bq[buf][0] = *reinterpret_cast<const uint4*>(p);
            bq[buf][1] = *reinterpret_cast<const uint4*>(p + 128);
        };

        loadA(0, 0);
        loadB(0, 0);

        // 8 half-slices; prefetch half i+1 before MMAs of half i
        #pragma unroll
        for (int i = 0; i < 8; i++) {
            const int ks = i >> 1, half = i & 1, buf = i & 1;
            if (i < 7) loadB(buf ^ 1, i + 1);
            if (half == 1 && ks < 3) loadA((ks & 1) ^ 1, ks + 1);
            const int ab = ks & 1;
            #pragma unroll
            for (int tm = 0; tm < 2; tm++)
                #pragma unroll
                for (int jj = 0; jj < 2; jj++) {
                    const int tn0 = (half * 2 + jj) * 2;
                    asm volatile(
                        "mma.sync.aligned.m16n8k16.row.col.f32.f16.f16.f32 "
                        "{%0,%1,%2,%3}, {%4,%5,%6,%7}, {%8,%9}, {%0,%1,%2,%3};"
                        : "+f"(acc[tm][tn0][0]), "+f"(acc[tm][tn0][1]),
                          "+f"(acc[tm][tn0][2]), "+f"(acc[tm][tn0][3])
                        : "r"(af[ab][tm][0]), "r"(af[ab][tm][1]),
                          "r"(af[ab][tm][2]), "r"(af[ab][tm][3]),
                          "r"(bq[buf][jj].x), "r"(bq[buf][jj].y));
                    asm volatile(
                        "mma.sync.aligned.m16n8k16.row.col.f32.f16.f16.f32 "
                        "{%0,%1,%2,%3}, {%4,%5,%6,%7}, {%8,%9}, {%0,%1,%2,%3};"
                        : "+f"(acc[tm][tn0 + 1][0]), "+f"(acc[tm][tn0 + 1][1]),
                          "+f"(acc[tm][tn0 + 1][2]), "+f"(acc[tm][tn0 + 1][3])
                        : "r"(af[ab][tm][0]), "r"(af[ab][tm][1]),
                          "r"(af[ab][tm][2]), "r"(af[ab][tm][3]),
                          "r"(bq[buf][jj].z), "r"(bq[buf][jj].w));
                }
        }

        // -------- epilogue at each ei boundary --------
        if ((g & 7) == 7) {
            const int ei = g >> 3;
            float lp[2][2] = {{0.f, 0.f}, {0.f, 0.f}};
            const int sg0 = s0 + warp_s * 32 + (lane >> 2);
            #pragma unroll
            for (int tm = 0; tm < 2; tm++) {
                const int srow = sg0 + tm * 16;
                #pragma unroll
                for (int tn = 0; tn < 8; tn++) {
                    const int e = ei * 128 + warp_e * 64 + tn * 8 + 2 * (lane & 3);
                    const float b0v = SM_BIAS(e), b1v = SM_BIAS(e + 1);
                    const float a0 = acc[tm][tn][0], a1 = acc[tm][tn][1];
                    const float a2 = acc[tm][tn][2], a3 = acc[tm][tn][3];
                    outr_b[(size_t)e       * S_DIM + srow]     = a0 + b0v;
                    outr_b[(size_t)(e + 1) * S_DIM + srow]     = a1 + b1v;
                    outr_b[(size_t)e       * S_DIM + srow + 8] = a2 + b0v;
                    outr_b[(size_t)(e + 1) * S_DIM + srow + 8] = a3 + b1v;
                    const float q0 = SM_QPB(e), q1 = SM_QPB(e + 1);
                    const float v0 = SM_V(e), v1 = SM_V(e + 1);
                    lp[tm][0] += tanha(q0 + a0) * v0 + tanha(q1 + a1) * v1;
                    lp[tm][1] += tanha(q0 + a2) * v0 + tanha(q1 + a3) * v1;
                    acc[tm][tn][0] = 0.f; acc[tm][tn][1] = 0.f;
                    acc[tm][tn][2] = 0.f; acc[tm][tn][3] = 0.f;
                }
            }
            #pragma unroll
            for (int tm = 0; tm < 2; tm++)
                #pragma unroll
                for (int h = 0; h < 2; h++) {
                    float v = lp[tm][h];
                    v += __shfl_xor_sync(0xffffffffu, v, 1);
                    v += __shfl_xor_sync(0xffffffffu, v, 2);
                    if ((lane & 3) == 0)
                        atomicAdd(&SM_L(warp_s * 32 + tm * 16 + h * 8 + (lane >> 2)), v);
                }
        }
    }

    __syncthreads();
    if (tid < BLK_S)
        out_logits[(size_t)b * S_DIM + s0 + tid] = 10.0f * tanha(SM_L(tid));
}

// ---------------------------------------------------------------------------
// launch
// ---------------------------------------------------------------------------
extern "C" void kernel_launch(void* const* d_in, const int* in_sizes, int n_in,
                              void* d_out, int out_size) {
    const float* query = (const float*)d_in[0];
    const float* ref   = (const float*)d_in[1];
    const float* Wq_w  = (const float*)d_in[2];
    const float* Wq_b  = (const float*)d_in[3];
    const float* Wr_w  = (const float*)d_in[4];
    const float* Wr_b  = (const float*)d_in[5];
    const float* value = (const float*)d_in[6];
    (void)in_sizes; (void)n_in; (void)out_size;

    float* out        = (float*)d_out;
    float* out_r      = out;                                   // [B, D, S]
    float* out_logits = out + (size_t)B_DIM * D_DIM * S_DIM;   // [B, S]

    prep_kernel<<<1280, 256>>>(Wr_w, query, Wq_w, Wq_b, Wr_b);

    const size_t smem = SMEM_WORDS * sizeof(float);
    cudaFuncSetAttribute(attn_main, cudaFuncAttributeMaxDynamicSharedMemorySize,
                         (int)smem);
    dim3 grid(S_DIM / BLK_S, B_DIM);
    attn_main<<<grid, NTHREADS, smem>>>(ref, Wr_b, value, out_r, out_logits);
}